// round 2
// baseline (speedup 1.0000x reference)
#include <cuda_runtime.h>

// LIF scan: v = v + (x - v)*0.5; s = (v >= 1); v = s ? 0 : v
// x: [B=64, T=200, N=4096] fp32 -> spikes same shape.
// Each thread owns 4 consecutive n (one float4 lane) for one b, walks T serially.
// T-loop unrolled by 8 to keep 8 independent 16B loads in flight (hide DRAM lat).

#define LIF_B 64
#define LIF_T 200
#define LIF_N 4096
#define NV (LIF_N / 4)   // 1024 float4 per (b, t) row

__device__ __forceinline__ void lif_step(float& v, float xx, float& s) {
    v = v + (xx - v) * 0.5f;          // exact match to ref op order (x0.5 exact)
    bool fire = (v >= 1.0f);
    s = fire ? 1.0f : 0.0f;
    v = fire ? 0.0f : v;
}

__device__ __forceinline__ void lif_step4(float4& v, const float4 x, float4& s) {
    lif_step(v.x, x.x, s.x);
    lif_step(v.y, x.y, s.y);
    lif_step(v.z, x.z, s.z);
    lif_step(v.w, x.w, s.w);
}

__global__ __launch_bounds__(128)
void lif_kernel(const float4* __restrict__ x, float4* __restrict__ out) {
    int idx = blockIdx.x * blockDim.x + threadIdx.x;   // 0 .. B*NV-1
    int b   = idx >> 10;          // / NV (NV = 1024)
    int n4  = idx & (NV - 1);

    size_t base = (size_t)b * LIF_T * NV + n4;
    const float4* xp = x + base;
    float4*       op = out + base;

    float4 v = make_float4(0.f, 0.f, 0.f, 0.f);

    #pragma unroll 1
    for (int t = 0; t < LIF_T; t += 8) {
        // Batch 8 independent loads first (MLP = 8)
        float4 x0 = __ldg(xp + 0 * NV);
        float4 x1 = __ldg(xp + 1 * NV);
        float4 x2 = __ldg(xp + 2 * NV);
        float4 x3 = __ldg(xp + 3 * NV);
        float4 x4 = __ldg(xp + 4 * NV);
        float4 x5 = __ldg(xp + 5 * NV);
        float4 x6 = __ldg(xp + 6 * NV);
        float4 x7 = __ldg(xp + 7 * NV);

        float4 s0, s1, s2, s3, s4, s5, s6, s7;
        lif_step4(v, x0, s0);
        lif_step4(v, x1, s1);
        lif_step4(v, x2, s2);
        lif_step4(v, x3, s3);
        lif_step4(v, x4, s4);
        lif_step4(v, x5, s5);
        lif_step4(v, x6, s6);
        lif_step4(v, x7, s7);

        op[0 * NV] = s0;
        op[1 * NV] = s1;
        op[2 * NV] = s2;
        op[3 * NV] = s3;
        op[4 * NV] = s4;
        op[5 * NV] = s5;
        op[6 * NV] = s6;
        op[7 * NV] = s7;

        xp += 8 * NV;
        op += 8 * NV;
    }
}

extern "C" void kernel_launch(void* const* d_in, const int* in_sizes, int n_in,
                              void* d_out, int out_size) {
    const float* x = (const float*)d_in[0];
    // d_in[1] = threshold param, unused by the reference forward
    float* out = (float*)d_out;

    const int total_threads = LIF_B * NV;   // 65536
    const int block = 128;
    lif_kernel<<<total_threads / block, block>>>(
        (const float4*)x, (float4*)out);
}

// round 3
// speedup vs baseline: 1.0857x; 1.0857x over previous
#include <cuda_runtime.h>

// LIF scan: v = v + (x - v)*0.5; s = (v >= 1); v = s ? 0 : v
// x: [B=64, T=200, N=4096] fp32 -> spikes same shape.
// Each thread owns 4 consecutive n (one float4) for one b, walks T serially.
// T-loop in groups of 8; software-pipelined (prefetch next group's 8 loads
// before computing/storing the current group) so DRAM reads stay in flight
// during the serial per-step dependency chain.
// grid=1024 blocks of 64 threads -> 6.92 blocks/SM, ~1% wave imbalance
// (vs 3.46 blocks/SM = 15% imbalance with 128-thread blocks).

#define LIF_B 64
#define LIF_T 200
#define LIF_N 4096
#define NV (LIF_N / 4)   // 1024 float4 per (b, t) row
#define G 8              // timesteps per group
#define NGROUP (LIF_T / G)  // 25

__device__ __forceinline__ void lif_step(float& v, float xx, float& s) {
    v = v + (xx - v) * 0.5f;          // exact match to ref op order (x0.5 exact)
    bool fire = (v >= 1.0f);
    s = fire ? 1.0f : 0.0f;
    v = fire ? 0.0f : v;
}

__device__ __forceinline__ void lif_step4_store(float4& v, const float4 x,
                                                float4* __restrict__ op) {
    float4 s;
    lif_step(v.x, x.x, s.x);
    lif_step(v.y, x.y, s.y);
    lif_step(v.z, x.z, s.z);
    lif_step(v.w, x.w, s.w);
    *op = s;
}

__device__ __forceinline__ void load_group(const float4* __restrict__ xp,
                                           float4 (&xr)[G]) {
    #pragma unroll
    for (int i = 0; i < G; i++) xr[i] = __ldg(xp + i * NV);
}

__device__ __forceinline__ void process_group(float4& v, const float4 (&xr)[G],
                                              float4* __restrict__ op) {
    #pragma unroll
    for (int i = 0; i < G; i++) lif_step4_store(v, xr[i], op + i * NV);
}

__global__ __launch_bounds__(64)
void lif_kernel(const float4* __restrict__ x, float4* __restrict__ out) {
    int idx = blockIdx.x * blockDim.x + threadIdx.x;   // 0 .. B*NV-1
    int b   = idx >> 10;          // / NV (NV = 1024)
    int n4  = idx & (NV - 1);

    size_t base = (size_t)b * LIF_T * NV + n4;
    const float4* xp = x + base;
    float4*       op = out + base;

    float4 v = make_float4(0.f, 0.f, 0.f, 0.f);
    float4 xa[G], xb[G];

    // prologue: load group 0
    load_group(xp, xa);

    // 24 groups in 12 double-iterations; each half prefetches the next group
    // before touching the serial compute chain of the current one.
    #pragma unroll 1
    for (int gg = 0; gg < (NGROUP - 1) / 2; gg++) {
        load_group(xp + G * NV, xb);        // prefetch group 2gg+1
        process_group(v, xa, op);           // compute+store group 2gg
        xp += G * NV; op += G * NV;

        load_group(xp + G * NV, xa);        // prefetch group 2gg+2
        process_group(v, xb, op);           // compute+store group 2gg+1
        xp += G * NV; op += G * NV;
    }

    // epilogue: group 24 (already loaded into xa)
    process_group(v, xa, op);
}

extern "C" void kernel_launch(void* const* d_in, const int* in_sizes, int n_in,
                              void* d_out, int out_size) {
    const float* x = (const float*)d_in[0];
    // d_in[1] = threshold param, unused by the reference forward
    float* out = (float*)d_out;

    const int total_threads = LIF_B * NV;   // 65536
    const int block = 64;
    lif_kernel<<<total_threads / block, block>>>(
        (const float4*)x, (float4*)out);
}